// round 1
// baseline (speedup 1.0000x reference)
#include <cuda_runtime.h>
#include <cuda_bf16.h>
#include <cstdint>

// Problem constants (shapes fixed by the dataset; row counts taken from in_sizes)
#define Hh 128
#define DAa 128
#define DMm 64

// ---------------- device scratch (allocation-free: device globals) ----------------
__device__ float g_W1[Hh * DAa];        // 64 KB   W1 = Wc1 @ Wp_a
__device__ float g_W2[Hh * DMm];        // 32 KB   W2 = Wc2 @ Wr_ma
__device__ float g_b1[Hh];
__device__ float g_b2[Hh];
__device__ float g_m2[100000 * Hh];     // 51.2 MB  m2 = x_m @ W2^T + b2
__device__ float g_acc[200000 * Hh];    // 102.4 MB z accumulator

// ---------------- kernel 1: fold the linear chain ----------------
// W1[h,d] = sum_k Wc_a[h,k]      * Wp_a[k,d]   (k<128, d<128)
// W2[h,d] = sum_k Wc_a[h,128+k]  * Wr_ma[k,d]  (k<128, d<64)
// b1[h]   = bc_a[h] + sum_k Wc_a[h,k]*bp_a[k]
// b2[h]   = sum_k Wc_a[h,128+k]*br_ma[k]
__global__ void fold_kernel(const float* __restrict__ Wc_a,
                            const float* __restrict__ Wp_a,
                            const float* __restrict__ Wr_ma,
                            const float* __restrict__ bp_a,
                            const float* __restrict__ bc_a,
                            const float* __restrict__ br_ma) {
    int h = blockIdx.x;        // 0..127
    int d = threadIdx.x;       // 0..127
    const float* wc1 = Wc_a + h * 256;
    const float* wc2 = wc1 + 128;

    float s = 0.f;
    #pragma unroll 8
    for (int k = 0; k < 128; ++k) s += wc1[k] * Wp_a[k * DAa + d];
    g_W1[h * DAa + d] = s;

    if (d < DMm) {
        float s2 = 0.f;
        #pragma unroll 8
        for (int k = 0; k < 128; ++k) s2 += wc2[k] * Wr_ma[k * DMm + d];
        g_W2[h * DMm + d] = s2;
    }
    if (d == 0) {
        float t1 = bc_a[h], t2 = 0.f;
        for (int k = 0; k < 128; ++k) {
            t1 += wc1[k] * bp_a[k];
            t2 += wc2[k] * br_ma[k];
        }
        g_b1[h] = t1;
        g_b2[h] = t2;
    }
}

// ---------------- kernel 2/3: C[M,128] = A[M,K] @ W[128,K]^T + bias ----------------
// Block: 256 threads, tile BM=64 rows x 128 cols. W staged transposed in smem,
// A tile staged with padded stride to dodge bank conflicts. Each thread: 4x8 regs.
template <int K, int KPAD>
__global__ void gemm_bias_kernel(const float* __restrict__ A, int M,
                                 const float* __restrict__ W,      // [128 x K]
                                 const float* __restrict__ bias,   // [128]
                                 float* __restrict__ C) {          // [M x 128]
    extern __shared__ float sm[];
    float* Wsh = sm;                 // [K][128]  (Wsh[d*128+h] = W[h*K+d])
    float* Ash = sm + K * 128;       // [64][KPAD]

    const int tid  = threadIdx.x;
    const int row0 = blockIdx.x * 64;

    // Load W transposed (coalesced global reads)
    for (int idx = tid; idx < K * 128; idx += 256) {
        int h = idx / K, d = idx - h * K;
        Wsh[d * 128 + h] = W[idx];
    }
    // Load A tile (row-guarded)
    for (int idx = tid; idx < 64 * K; idx += 256) {
        int r = idx / K, d = idx - r * K;
        int gi = row0 + r;
        Ash[r * KPAD + d] = (gi < M) ? A[(size_t)gi * K + d] : 0.f;
    }
    __syncthreads();

    const int tx = tid & 15;   // col group (8 cols)
    const int ty = tid >> 4;   // row group (4 rows)
    const int c0 = tx * 8;
    const int r0 = ty * 4;

    float acc[4][8];
    {
        float bb[8];
        #pragma unroll
        for (int j = 0; j < 8; ++j) bb[j] = bias[c0 + j];
        #pragma unroll
        for (int r = 0; r < 4; ++r)
            #pragma unroll
            for (int j = 0; j < 8; ++j) acc[r][j] = bb[j];
    }

    #pragma unroll 4
    for (int k = 0; k < K; ++k) {
        float a0 = Ash[(r0 + 0) * KPAD + k];
        float a1 = Ash[(r0 + 1) * KPAD + k];
        float a2 = Ash[(r0 + 2) * KPAD + k];
        float a3 = Ash[(r0 + 3) * KPAD + k];
        float4 w0 = *reinterpret_cast<const float4*>(&Wsh[k * 128 + c0]);
        float4 w1 = *reinterpret_cast<const float4*>(&Wsh[k * 128 + c0 + 4]);
        float wv[8] = {w0.x, w0.y, w0.z, w0.w, w1.x, w1.y, w1.z, w1.w};
        float av[4] = {a0, a1, a2, a3};
        #pragma unroll
        for (int r = 0; r < 4; ++r)
            #pragma unroll
            for (int j = 0; j < 8; ++j) acc[r][j] += av[r] * wv[j];
    }

    #pragma unroll
    for (int r = 0; r < 4; ++r) {
        int gi = row0 + r0 + r;
        if (gi < M) {
            float4 o0 = make_float4(acc[r][0], acc[r][1], acc[r][2], acc[r][3]);
            float4 o1 = make_float4(acc[r][4], acc[r][5], acc[r][6], acc[r][7]);
            float4* cp = reinterpret_cast<float4*>(C + (size_t)gi * 128 + c0);
            cp[0] = o0;
            cp[1] = o1;
        }
    }
}

// ---------------- kernel 4: edge scatter, one warp per edge ----------------
// acc[dst] += w * m2[src]   (128 floats = 32 lanes x float4, vector red)
__global__ void scatter_kernel(const int* __restrict__ src,
                               const int* __restrict__ dst,
                               const float* __restrict__ w,
                               const float* __restrict__ m2,
                               float* __restrict__ acc, int E) {
    int warp = (blockIdx.x * blockDim.x + threadIdx.x) >> 5;
    int lane = threadIdx.x & 31;
    if (warp >= E) return;
    int   s  = src[warp];
    int   d  = dst[warp];
    float we = w[warp];
    float4 v = reinterpret_cast<const float4*>(m2 + (size_t)s * 128)[lane];
    float* out = acc + (size_t)d * 128 + lane * 4;
    asm volatile("red.global.add.v4.f32 [%0], {%1, %2, %3, %4};"
                 :: "l"(out), "f"(v.x * we), "f"(v.y * we),
                    "f"(v.z * we), "f"(v.w * we)
                 : "memory");
}

// ---------------- kernel 5: head — out[i] = sigmoid(Wo . relu(acc[i]) + bo) ----------------
__global__ void head_kernel(const float* __restrict__ acc,
                            const float* __restrict__ Wo,
                            const float* __restrict__ bo,
                            float* __restrict__ out, int M) {
    int warp = (blockIdx.x * blockDim.x + threadIdx.x) >> 5;
    int lane = threadIdx.x & 31;
    if (warp >= M) return;
    float4 a = reinterpret_cast<const float4*>(acc + (size_t)warp * 128)[lane];
    float4 w = reinterpret_cast<const float4*>(Wo)[lane];
    float p = fmaxf(a.x, 0.f) * w.x + fmaxf(a.y, 0.f) * w.y +
              fmaxf(a.z, 0.f) * w.z + fmaxf(a.w, 0.f) * w.w;
    #pragma unroll
    for (int off = 16; off > 0; off >>= 1)
        p += __shfl_xor_sync(0xFFFFFFFFu, p, off);
    if (lane == 0) {
        float z = p + bo[0];
        out[warp] = 1.f / (1.f + expf(-z));
    }
}

// ---------------- launch ----------------
extern "C" void kernel_launch(void* const* d_in, const int* in_sizes, int n_in,
                              void* d_out, int out_size) {
    const float* x_account = (const float*)d_in[0];
    const float* x_merchant = (const float*)d_in[1];
    // d_in[2..4]: e_am_* — dead code (only the account head is returned)
    const int*   e_ma_src = (const int*)d_in[5];
    const int*   e_ma_dst = (const int*)d_in[6];
    const float* e_ma_w   = (const float*)d_in[7];
    const float* Wp_a  = (const float*)d_in[8];
    const float* bp_a  = (const float*)d_in[9];
    // d_in[10..13]: Wp_m/bp_m/Wr_am/br_am — dead code
    const float* Wr_ma = (const float*)d_in[14];
    const float* br_ma = (const float*)d_in[15];
    const float* Wc_a  = (const float*)d_in[16];
    const float* bc_a  = (const float*)d_in[17];
    // d_in[18..19]: Wc_m/bc_m — dead code
    const float* Wo = (const float*)d_in[20];
    const float* bo = (const float*)d_in[21];
    float* out = (float*)d_out;

    const int NA = in_sizes[0] / DAa;   // 200000
    const int NM = in_sizes[1] / DMm;   // 100000
    const int E  = in_sizes[5];         // 1000000

    float *pW1, *pW2, *pb1, *pb2, *pm2, *pacc;
    cudaGetSymbolAddress((void**)&pW1, g_W1);
    cudaGetSymbolAddress((void**)&pW2, g_W2);
    cudaGetSymbolAddress((void**)&pb1, g_b1);
    cudaGetSymbolAddress((void**)&pb2, g_b2);
    cudaGetSymbolAddress((void**)&pm2, g_m2);
    cudaGetSymbolAddress((void**)&pacc, g_acc);

    constexpr int SMEM_128 = (128 * 128 + 64 * 132) * 4;  // 99328 B
    constexpr int SMEM_64  = (64 * 128 + 64 * 68) * 4;    // 50176 B
    cudaFuncSetAttribute(gemm_bias_kernel<128, 132>,
                         cudaFuncAttributeMaxDynamicSharedMemorySize, SMEM_128);
    cudaFuncSetAttribute(gemm_bias_kernel<64, 68>,
                         cudaFuncAttributeMaxDynamicSharedMemorySize, SMEM_64);

    // 1. fold weights
    fold_kernel<<<128, 128>>>(Wc_a, Wp_a, Wr_ma, bp_a, bc_a, br_ma);

    // 2. m2 = x_m @ W2^T + b2
    gemm_bias_kernel<64, 68><<<(NM + 63) / 64, 256, SMEM_64>>>(
        x_merchant, NM, pW2, pb2, pm2);

    // 3. acc = x_a @ W1^T + b1
    gemm_bias_kernel<128, 132><<<(NA + 63) / 64, 256, SMEM_128>>>(
        x_account, NA, pW1, pb1, pacc);

    // 4. scatter edges (merchant -> account)
    scatter_kernel<<<(E + 7) / 8, 256>>>(e_ma_src, e_ma_dst, e_ma_w, pm2, pacc, E);

    // 5. head
    head_kernel<<<(NA + 7) / 8, 256>>>(pacc, Wo, bo, out, NA);
}

// round 3
// speedup vs baseline: 1.8697x; 1.8697x over previous
#include <cuda_runtime.h>
#include <cuda_bf16.h>
#include <cstdint>

#define Hh 128
#define DAa 128
#define DMm 64
#define NA_MAX 200000
#define NM_MAX 100000

// ---------------- device scratch (allocation-free: device globals) ----------------
__device__ float         g_b1[Hh];
__device__ float         g_b2[Hh];
__device__ __nv_bfloat16 g_W1h[Hh * DAa];        // 32 KB  W1 = Wc1 @ Wp_a  (bf16)
__device__ __nv_bfloat16 g_W2h[Hh * DMm];        // 16 KB  W2 = Wc2 @ Wr_ma (bf16)
__device__ __nv_bfloat16 g_m2[NM_MAX * Hh];      // 25.6 MB  m2 = x_m @ W2^T + b2 (bf16)
__device__ float         g_acc[NA_MAX * Hh];     // 102.4 MB z accumulator (fp32)

__device__ __forceinline__ uint32_t smem_u32(const void* p) {
    uint32_t a;
    asm("{ .reg .u64 t; cvta.to.shared.u64 t, %1; cvt.u32.u64 %0, t; }" : "=r"(a) : "l"(p));
    return a;
}

#define LDMATRIX_X4(r0, r1, r2, r3, addr) \
    asm volatile("ldmatrix.sync.aligned.m8n8.x4.shared.b16 {%0,%1,%2,%3}, [%4];" \
                 : "=r"(r0), "=r"(r1), "=r"(r2), "=r"(r3) : "r"(addr))

#define MMA_BF16(c, a0, a1, a2, a3, b0, b1) \
    asm volatile("mma.sync.aligned.m16n8k16.row.col.f32.bf16.bf16.f32 " \
                 "{%0,%1,%2,%3}, {%4,%5,%6,%7}, {%8,%9}, {%0,%1,%2,%3};" \
                 : "+f"((c)[0]), "+f"((c)[1]), "+f"((c)[2]), "+f"((c)[3]) \
                 : "r"(a0), "r"(a1), "r"(a2), "r"(a3), "r"(b0), "r"(b1))

// ---------------- kernel 1: fold the linear chain ----------------
// W1 = Wc1 @ Wp_a (bf16 out), W2 = Wc2 @ Wr_ma (bf16 out), folded biases fp32.
__global__ void fold_kernel(const float* __restrict__ Wc_a,
                            const float* __restrict__ Wp_a,
                            const float* __restrict__ Wr_ma,
                            const float* __restrict__ bp_a,
                            const float* __restrict__ bc_a,
                            const float* __restrict__ br_ma) {
    int h = blockIdx.x;        // 0..127
    int d = threadIdx.x;       // 0..127
    const float* wc1 = Wc_a + h * 256;
    const float* wc2 = wc1 + 128;

    float s = 0.f;
    #pragma unroll 8
    for (int k = 0; k < 128; ++k) s += wc1[k] * Wp_a[k * DAa + d];
    g_W1h[h * DAa + d] = __float2bfloat16(s);

    if (d < DMm) {
        float s2 = 0.f;
        #pragma unroll 8
        for (int k = 0; k < 128; ++k) s2 += wc2[k] * Wr_ma[k * DMm + d];
        g_W2h[h * DMm + d] = __float2bfloat16(s2);
    }
    if (d == 0) {
        float t1 = bc_a[h], t2 = 0.f;
        for (int k = 0; k < 128; ++k) {
            t1 += wc1[k] * bp_a[k];
            t2 += wc2[k] * br_ma[k];
        }
        g_b1[h] = t1;
        g_b2[h] = t2;
    }
}

// ---------------- kernels 2/3: warp-MMA GEMM  C[M,128] = bf16(A[M,K]) @ Wh^T + bias ----
// 256 threads, 128-row x 128-col tile per CTA. Each warp: m16 x n128.
// A fp32->bf16 into smem (padded stride, ldmatrix conflict-free), W bf16 staged same.
template <int K, bool OUT_BF16>
__global__ void __launch_bounds__(256)
mma_gemm_kernel(const float* __restrict__ A, int M,
                const __nv_bfloat16* __restrict__ W,     // [128 x K] bf16 row-major
                const float* __restrict__ bias,          // [128]
                void* __restrict__ Cout) {
    constexpr int RS = K * 2 + 16;           // padded row stride (bytes); 17/9 x16B chunks
    constexpr int TILE_B = 128 * RS;
    constexpr int WPR = K / 2;               // 4-byte words per row
    extern __shared__ char smem[];
    char*  smA   = smem;
    char*  smW   = smem + TILE_B;
    float* sbias = (float*)(smem + 2 * TILE_B);

    const int tid = threadIdx.x, wid = tid >> 5, lane = tid & 31;
    const int row0 = blockIdx.x * 128;

    // stage W (already bf16)
    for (int idx = tid; idx < 128 * WPR; idx += 256) {
        int r = idx / WPR, p = idx - r * WPR;
        *(uint32_t*)(smW + r * RS + p * 4) = ((const uint32_t*)W)[idx];
    }
    // stage A with fp32->bf16 conversion
    for (int idx = tid; idx < 128 * WPR; idx += 256) {
        int r = idx / WPR, p = idx - r * WPR;
        int gr = row0 + r;
        float2 av = (gr < M) ? ((const float2*)(A + (size_t)gr * K))[p]
                             : make_float2(0.f, 0.f);
        uint32_t pv;
        asm("cvt.rn.bf16x2.f32 %0, %1, %2;" : "=r"(pv) : "f"(av.y), "f"(av.x));
        *(uint32_t*)(smA + r * RS + p * 4) = pv;
    }
    if (tid < 128) sbias[tid] = bias[tid];
    __syncthreads();

    // ldmatrix lane address bases
    // A x4: rows (wid*16 + (lane&15)), k-half = lane>>4
    const uint32_t aBase = smem_u32(smA)
        + (uint32_t)(wid * 16 + (lane & 15)) * RS + (uint32_t)(lane >> 4) * 16;
    // B x4 (two n-tiles per load): n = (lane&7) + ((lane>>4)<<3), k-half = (lane>>3)&1
    const uint32_t bBase = smem_u32(smW)
        + (uint32_t)((lane & 7) + ((lane >> 4) << 3)) * RS
        + (uint32_t)((lane >> 3) & 1) * 16;

    float acc[16][4];
    #pragma unroll
    for (int i = 0; i < 16; ++i)
        #pragma unroll
        for (int j = 0; j < 4; ++j) acc[i][j] = 0.f;

    #pragma unroll
    for (int ks = 0; ks < K / 16; ++ks) {
        uint32_t a0, a1, a2, a3;
        LDMATRIX_X4(a0, a1, a2, a3, aBase + (uint32_t)ks * 32);
        #pragma unroll
        for (int jp = 0; jp < 8; ++jp) {
            uint32_t b0, b1, b2, b3;
            LDMATRIX_X4(b0, b1, b2, b3, bBase + (uint32_t)(jp * 16) * RS + (uint32_t)ks * 32);
            MMA_BF16(acc[2 * jp],     a0, a1, a2, a3, b0, b1);
            MMA_BF16(acc[2 * jp + 1], a0, a1, a2, a3, b2, b3);
        }
    }

    // Epilogue: thread (g=lane>>2, t=lane&3) owns rows g,g+8 and cols {2t,2t+1} per n-tile
    const int g = lane >> 2, t = lane & 3;
    const int r_lo = row0 + wid * 16 + g;
    const int r_hi = r_lo + 8;
    const bool lo_ok = r_lo < M, hi_ok = r_hi < M;

    #pragma unroll
    for (int nt = 0; nt < 16; ++nt) {
        int col = nt * 8 + 2 * t;
        float bx = sbias[col], by = sbias[col + 1];
        float c0 = acc[nt][0] + bx, c1 = acc[nt][1] + by;
        float c2 = acc[nt][2] + bx, c3 = acc[nt][3] + by;
        if (OUT_BF16) {
            __nv_bfloat16* C = (__nv_bfloat16*)Cout;
            uint32_t plo, phi;
            asm("cvt.rn.bf16x2.f32 %0, %1, %2;" : "=r"(plo) : "f"(c1), "f"(c0));
            asm("cvt.rn.bf16x2.f32 %0, %1, %2;" : "=r"(phi) : "f"(c3), "f"(c2));
            if (lo_ok) *(uint32_t*)(C + (size_t)r_lo * 128 + col) = plo;
            if (hi_ok) *(uint32_t*)(C + (size_t)r_hi * 128 + col) = phi;
        } else {
            float* C = (float*)Cout;
            if (lo_ok) *(float2*)(C + (size_t)r_lo * 128 + col) = make_float2(c0, c1);
            if (hi_ok) *(float2*)(C + (size_t)r_hi * 128 + col) = make_float2(c2, c3);
        }
    }
}

// ---------------- kernel 4: edge scatter (dst-range pass), one warp per edge -----------
// acc[dst] += w * float(m2_bf16[src])  — 128 floats = 32 lanes x red.v4
__global__ void scatter_kernel(const int* __restrict__ src,
                               const int* __restrict__ dst,
                               const float* __restrict__ w,
                               const __nv_bfloat16* __restrict__ m2,
                               float* __restrict__ acc, int E,
                               int dlo, int dhi) {
    int warp = (blockIdx.x * blockDim.x + threadIdx.x) >> 5;
    int lane = threadIdx.x & 31;
    if (warp >= E) return;
    int d = dst[warp];
    if (d < dlo || d >= dhi) return;
    int   s  = src[warp];
    float we = w[warp];
    uint2 q = ((const uint2*)(m2 + (size_t)s * 128))[lane];
    __nv_bfloat162 b0 = *reinterpret_cast<__nv_bfloat162*>(&q.x);
    __nv_bfloat162 b1 = *reinterpret_cast<__nv_bfloat162*>(&q.y);
    float2 f0 = __bfloat1622float2(b0);
    float2 f1 = __bfloat1622float2(b1);
    float* out = acc + (size_t)d * 128 + lane * 4;
    asm volatile("red.global.add.v4.f32 [%0], {%1, %2, %3, %4};"
                 :: "l"(out), "f"(f0.x * we), "f"(f0.y * we),
                    "f"(f1.x * we), "f"(f1.y * we)
                 : "memory");
}

// ---------------- kernel 5: head — out[i] = sigmoid(Wo . relu(acc[i]) + bo) ------------
__global__ void head_kernel(const float* __restrict__ acc,
                            const float* __restrict__ Wo,
                            const float* __restrict__ bo,
                            float* __restrict__ out, int M) {
    int warp = (blockIdx.x * blockDim.x + threadIdx.x) >> 5;
    int lane = threadIdx.x & 31;
    if (warp >= M) return;
    float4 a = ((const float4*)(acc + (size_t)warp * 128))[lane];
    float4 w = ((const float4*)Wo)[lane];
    float p = fmaxf(a.x, 0.f) * w.x + fmaxf(a.y, 0.f) * w.y +
              fmaxf(a.z, 0.f) * w.z + fmaxf(a.w, 0.f) * w.w;
    #pragma unroll
    for (int off = 16; off > 0; off >>= 1)
        p += __shfl_xor_sync(0xFFFFFFFFu, p, off);
    if (lane == 0) {
        float z = p + bo[0];
        out[warp] = 1.f / (1.f + expf(-z));
    }
}

// ---------------- launch ----------------
extern "C" void kernel_launch(void* const* d_in, const int* in_sizes, int n_in,
                              void* d_out, int out_size) {
    const float* x_account  = (const float*)d_in[0];
    const float* x_merchant = (const float*)d_in[1];
    const int*   e_ma_src = (const int*)d_in[5];
    const int*   e_ma_dst = (const int*)d_in[6];
    const float* e_ma_w   = (const float*)d_in[7];
    const float* Wp_a  = (const float*)d_in[8];
    const float* bp_a  = (const float*)d_in[9];
    const float* Wr_ma = (const float*)d_in[14];
    const float* br_ma = (const float*)d_in[15];
    const float* Wc_a  = (const float*)d_in[16];
    const float* bc_a  = (const float*)d_in[17];
    const float* Wo = (const float*)d_in[20];
    const float* bo = (const float*)d_in[21];
    float* out = (float*)d_out;

    const int NA = in_sizes[0] / DAa;   // 200000
    const int NM = in_sizes[1] / DMm;   // 100000
    const int E  = in_sizes[5];         // 1000000

    float *pb1, *pb2, *pacc;
    __nv_bfloat16 *pW1h, *pW2h, *pm2;
    cudaGetSymbolAddress((void**)&pb1, g_b1);
    cudaGetSymbolAddress((void**)&pb2, g_b2);
    cudaGetSymbolAddress((void**)&pW1h, g_W1h);
    cudaGetSymbolAddress((void**)&pW2h, g_W2h);
    cudaGetSymbolAddress((void**)&pm2, g_m2);
    cudaGetSymbolAddress((void**)&pacc, g_acc);

    constexpr int SMEM_K128 = 2 * 128 * (128 * 2 + 16) + 512;   // 70144 B
    constexpr int SMEM_K64  = 2 * 128 * (64 * 2 + 16) + 512;    // 37376 B
    cudaFuncSetAttribute(mma_gemm_kernel<128, false>,
                         cudaFuncAttributeMaxDynamicSharedMemorySize, SMEM_K128);
    cudaFuncSetAttribute(mma_gemm_kernel<64, true>,
                         cudaFuncAttributeMaxDynamicSharedMemorySize, SMEM_K64);

    // 1. fold weights
    fold_kernel<<<128, 128>>>(Wc_a, Wp_a, Wr_ma, bp_a, bc_a, br_ma);

    // 2. m2 = bf16(x_m @ W2^T + b2)
    mma_gemm_kernel<64, true><<<(NM + 127) / 128, 256, SMEM_K64>>>(
        x_merchant, NM, pW2h, pb2, pm2);

    // 3. acc = x_a @ W1^T + b1   (fp32 out)
    mma_gemm_kernel<128, false><<<(NA + 127) / 128, 256, SMEM_K128>>>(
        x_account, NA, pW1h, pb1, pacc);

    // 4. scatter edges, two dst-range passes for L2 residency of acc
    int half = NA / 2;
    scatter_kernel<<<(E + 7) / 8, 256>>>(e_ma_src, e_ma_dst, e_ma_w, pm2, pacc, E, 0, half);
    scatter_kernel<<<(E + 7) / 8, 256>>>(e_ma_src, e_ma_dst, e_ma_w, pm2, pacc, E, half, NA);

    // 5. head
    head_kernel<<<(NA + 7) / 8, 256>>>(pacc, Wo, bo, out, NA);
}

// round 4
// speedup vs baseline: 3.1444x; 1.6818x over previous
#include <cuda_runtime.h>
#include <cuda_bf16.h>
#include <cstdint>

#define Hh 128
#define DAa 128
#define DMm 64
#define NA_MAX 200000
#define NM_MAX 100000

// ---------------- device scratch (allocation-free: device globals) ----------------
__device__ float         g_b1[Hh];
__device__ float         g_b2[Hh];
__device__ __nv_bfloat16 g_W1h[Hh * DAa];        // 32 KB  W1 = Wc1 @ Wp_a  (bf16)
__device__ __nv_bfloat16 g_W2h[Hh * DMm];        // 16 KB  W2 = Wc2 @ Wr_ma (bf16)
__device__ __nv_bfloat16 g_m2[NM_MAX * Hh];      // 25.6 MB  m2 = x_m @ W2^T + b2 (bf16)
__device__ float         g_acc[NA_MAX * Hh];     // 102.4 MB z accumulator (fp32)

__device__ __forceinline__ uint32_t smem_u32(const void* p) {
    uint32_t a;
    asm("{ .reg .u64 t; cvta.to.shared.u64 t, %1; cvt.u32.u64 %0, t; }" : "=r"(a) : "l"(p));
    return a;
}

#define LDMATRIX_X4(r0, r1, r2, r3, addr) \
    asm volatile("ldmatrix.sync.aligned.m8n8.x4.shared.b16 {%0,%1,%2,%3}, [%4];" \
                 : "=r"(r0), "=r"(r1), "=r"(r2), "=r"(r3) : "r"(addr))

#define MMA_BF16(c, a0, a1, a2, a3, b0, b1) \
    asm volatile("mma.sync.aligned.m16n8k16.row.col.f32.bf16.bf16.f32 " \
                 "{%0,%1,%2,%3}, {%4,%5,%6,%7}, {%8,%9}, {%0,%1,%2,%3};" \
                 : "+f"((c)[0]), "+f"((c)[1]), "+f"((c)[2]), "+f"((c)[3]) \
                 : "r"(a0), "r"(a1), "r"(a2), "r"(a3), "r"(b0), "r"(b1))

// ---------------- kernel 1: fold the linear chain ----------------
__global__ void fold_kernel(const float* __restrict__ Wc_a,
                            const float* __restrict__ Wp_a,
                            const float* __restrict__ Wr_ma,
                            const float* __restrict__ bp_a,
                            const float* __restrict__ bc_a,
                            const float* __restrict__ br_ma) {
    int h = blockIdx.x;        // 0..127
    int d = threadIdx.x;       // 0..127
    const float* wc1 = Wc_a + h * 256;
    const float* wc2 = wc1 + 128;

    float s = 0.f;
    #pragma unroll 8
    for (int k = 0; k < 128; ++k) s += wc1[k] * Wp_a[k * DAa + d];
    g_W1h[h * DAa + d] = __float2bfloat16(s);

    if (d < DMm) {
        float s2 = 0.f;
        #pragma unroll 8
        for (int k = 0; k < 128; ++k) s2 += wc2[k] * Wr_ma[k * DMm + d];
        g_W2h[h * DMm + d] = __float2bfloat16(s2);
    }
    if (d == 0) {
        float t1 = bc_a[h], t2 = 0.f;
        for (int k = 0; k < 128; ++k) {
            t1 += wc1[k] * bp_a[k];
            t2 += wc2[k] * br_ma[k];
        }
        g_b1[h] = t1;
        g_b2[h] = t2;
    }
}

// ---------------- kernels 2/3: warp-MMA GEMM  C[M,128] = bf16(A[M,K]) @ Wh^T + bias ----
template <int K, bool OUT_BF16>
__global__ void __launch_bounds__(256)
mma_gemm_kernel(const float* __restrict__ A, int M,
                const __nv_bfloat16* __restrict__ W,     // [128 x K] bf16 row-major
                const float* __restrict__ bias,          // [128]
                void* __restrict__ Cout) {
    constexpr int RS = K * 2 + 16;           // padded row stride (bytes)
    constexpr int TILE_B = 128 * RS;
    constexpr int WPR = K / 2;               // 4-byte words per row
    extern __shared__ char smem[];
    char*  smA   = smem;
    char*  smW   = smem + TILE_B;
    float* sbias = (float*)(smem + 2 * TILE_B);

    const int tid = threadIdx.x, wid = tid >> 5, lane = tid & 31;
    const int row0 = blockIdx.x * 128;

    for (int idx = tid; idx < 128 * WPR; idx += 256) {
        int r = idx / WPR, p = idx - r * WPR;
        *(uint32_t*)(smW + r * RS + p * 4) = ((const uint32_t*)W)[idx];
    }
    for (int idx = tid; idx < 128 * WPR; idx += 256) {
        int r = idx / WPR, p = idx - r * WPR;
        int gr = row0 + r;
        float2 av = (gr < M) ? ((const float2*)(A + (size_t)gr * K))[p]
                             : make_float2(0.f, 0.f);
        uint32_t pv;
        asm("cvt.rn.bf16x2.f32 %0, %1, %2;" : "=r"(pv) : "f"(av.y), "f"(av.x));
        *(uint32_t*)(smA + r * RS + p * 4) = pv;
    }
    if (tid < 128) sbias[tid] = bias[tid];
    __syncthreads();

    const uint32_t aBase = smem_u32(smA)
        + (uint32_t)(wid * 16 + (lane & 15)) * RS + (uint32_t)(lane >> 4) * 16;
    const uint32_t bBase = smem_u32(smW)
        + (uint32_t)((lane & 7) + ((lane >> 4) << 3)) * RS
        + (uint32_t)((lane >> 3) & 1) * 16;

    float acc[16][4];
    #pragma unroll
    for (int i = 0; i < 16; ++i)
        #pragma unroll
        for (int j = 0; j < 4; ++j) acc[i][j] = 0.f;

    #pragma unroll
    for (int ks = 0; ks < K / 16; ++ks) {
        uint32_t a0, a1, a2, a3;
        LDMATRIX_X4(a0, a1, a2, a3, aBase + (uint32_t)ks * 32);
        #pragma unroll
        for (int jp = 0; jp < 8; ++jp) {
            uint32_t b0, b1, b2, b3;
            LDMATRIX_X4(b0, b1, b2, b3, bBase + (uint32_t)(jp * 16) * RS + (uint32_t)ks * 32);
            MMA_BF16(acc[2 * jp],     a0, a1, a2, a3, b0, b1);
            MMA_BF16(acc[2 * jp + 1], a0, a1, a2, a3, b2, b3);
        }
    }

    const int g = lane >> 2, t = lane & 3;
    const int r_lo = row0 + wid * 16 + g;
    const int r_hi = r_lo + 8;
    const bool lo_ok = r_lo < M, hi_ok = r_hi < M;

    #pragma unroll
    for (int nt = 0; nt < 16; ++nt) {
        int col = nt * 8 + 2 * t;
        float bx = sbias[col], by = sbias[col + 1];
        float c0 = acc[nt][0] + bx, c1 = acc[nt][1] + by;
        float c2 = acc[nt][2] + bx, c3 = acc[nt][3] + by;
        if (OUT_BF16) {
            __nv_bfloat16* C = (__nv_bfloat16*)Cout;
            uint32_t plo, phi;
            asm("cvt.rn.bf16x2.f32 %0, %1, %2;" : "=r"(plo) : "f"(c1), "f"(c0));
            asm("cvt.rn.bf16x2.f32 %0, %1, %2;" : "=r"(phi) : "f"(c3), "f"(c2));
            if (lo_ok) *(uint32_t*)(C + (size_t)r_lo * 128 + col) = plo;
            if (hi_ok) *(uint32_t*)(C + (size_t)r_hi * 128 + col) = phi;
        } else {
            float* C = (float*)Cout;
            if (lo_ok) *(float2*)(C + (size_t)r_lo * 128 + col) = make_float2(c0, c1);
            if (hi_ok) *(float2*)(C + (size_t)r_hi * 128 + col) = make_float2(c2, c3);
        }
    }
}

// ---------------- kernel 4: batched edge scatter, 32 edges per warp -----------------
// Lanes co-load 32 edge triples (coalesced), shfl-broadcast, 8-deep pipelined
// gather -> red. Tail edges neutralized with w=0 (branchless exact zero add).
__global__ void __launch_bounds__(256)
scatter_kernel(const int* __restrict__ src,
               const int* __restrict__ dst,
               const float* __restrict__ w,
               const __nv_bfloat16* __restrict__ m2,
               float* __restrict__ acc, int E) {
    const int lane = threadIdx.x & 31;
    const int gwarp = (blockIdx.x * blockDim.x + threadIdx.x) >> 5;
    const int base = gwarp * 32;
    if (base >= E) return;

    int idx = base + lane;
    bool ok = idx < E;
    int   sl = ok ? src[idx] : 0;
    int   dl = ok ? dst[idx] : 0;
    float wl = ok ? w[idx]   : 0.f;

    const uint32_t lane8  = (uint32_t)lane * 8u;    // byte offset into 256B row (gather)
    const uint32_t lane16 = (uint32_t)lane * 16u;   // byte offset into 512B row (red)

    #pragma unroll
    for (int j0 = 0; j0 < 32; j0 += 8) {
        uint2 q[8];
        int   dj[8];
        float wj[8];
        #pragma unroll
        for (int j = 0; j < 8; ++j) {
            int   sj = __shfl_sync(0xFFFFFFFFu, sl, j0 + j);
            dj[j]    = __shfl_sync(0xFFFFFFFFu, dl, j0 + j);
            wj[j]    = __shfl_sync(0xFFFFFFFFu, wl, j0 + j);
            q[j] = *(const uint2*)((const char*)m2 + (size_t)sj * 256 + lane8);
        }
        #pragma unroll
        for (int j = 0; j < 8; ++j) {
            __nv_bfloat162 b0 = *reinterpret_cast<__nv_bfloat162*>(&q[j].x);
            __nv_bfloat162 b1 = *reinterpret_cast<__nv_bfloat162*>(&q[j].y);
            float2 f0 = __bfloat1622float2(b0);
            float2 f1 = __bfloat1622float2(b1);
            float we = wj[j];
            float* out = (float*)((char*)acc + (size_t)dj[j] * 512 + lane16);
            asm volatile("red.global.add.v4.f32 [%0], {%1, %2, %3, %4};"
                         :: "l"(out), "f"(f0.x * we), "f"(f0.y * we),
                            "f"(f1.x * we), "f"(f1.y * we)
                         : "memory");
        }
    }
}

// ---------------- kernel 5: head — out[i] = sigmoid(Wo . relu(acc[i]) + bo) ------------
__global__ void head_kernel(const float* __restrict__ acc,
                            const float* __restrict__ Wo,
                            const float* __restrict__ bo,
                            float* __restrict__ out, int M) {
    int warp = (blockIdx.x * blockDim.x + threadIdx.x) >> 5;
    int lane = threadIdx.x & 31;
    if (warp >= M) return;
    float4 a = ((const float4*)(acc + (size_t)warp * 128))[lane];
    float4 w = ((const float4*)Wo)[lane];
    float p = fmaxf(a.x, 0.f) * w.x + fmaxf(a.y, 0.f) * w.y +
              fmaxf(a.z, 0.f) * w.z + fmaxf(a.w, 0.f) * w.w;
    #pragma unroll
    for (int off = 16; off > 0; off >>= 1)
        p += __shfl_xor_sync(0xFFFFFFFFu, p, off);
    if (lane == 0) {
        float z = p + bo[0];
        out[warp] = 1.f / (1.f + expf(-z));
    }
}

// ---------------- launch ----------------
extern "C" void kernel_launch(void* const* d_in, const int* in_sizes, int n_in,
                              void* d_out, int out_size) {
    const float* x_account  = (const float*)d_in[0];
    const float* x_merchant = (const float*)d_in[1];
    const int*   e_ma_src = (const int*)d_in[5];
    const int*   e_ma_dst = (const int*)d_in[6];
    const float* e_ma_w   = (const float*)d_in[7];
    const float* Wp_a  = (const float*)d_in[8];
    const float* bp_a  = (const float*)d_in[9];
    const float* Wr_ma = (const float*)d_in[14];
    const float* br_ma = (const float*)d_in[15];
    const float* Wc_a  = (const float*)d_in[16];
    const float* bc_a  = (const float*)d_in[17];
    const float* Wo = (const float*)d_in[20];
    const float* bo = (const float*)d_in[21];
    float* out = (float*)d_out;

    const int NA = in_sizes[0] / DAa;   // 200000
    const int NM = in_sizes[1] / DMm;   // 100000
    const int E  = in_sizes[5];         // 1000000

    float *pb1, *pb2, *pacc;
    __nv_bfloat16 *pW1h, *pW2h, *pm2;
    cudaGetSymbolAddress((void**)&pb1, g_b1);
    cudaGetSymbolAddress((void**)&pb2, g_b2);
    cudaGetSymbolAddress((void**)&pW1h, g_W1h);
    cudaGetSymbolAddress((void**)&pW2h, g_W2h);
    cudaGetSymbolAddress((void**)&pm2, g_m2);
    cudaGetSymbolAddress((void**)&pacc, g_acc);

    constexpr int SMEM_K128 = 2 * 128 * (128 * 2 + 16) + 512;   // 70144 B
    constexpr int SMEM_K64  = 2 * 128 * (64 * 2 + 16) + 512;    // 37376 B
    cudaFuncSetAttribute(mma_gemm_kernel<128, false>,
                         cudaFuncAttributeMaxDynamicSharedMemorySize, SMEM_K128);
    cudaFuncSetAttribute(mma_gemm_kernel<64, true>,
                         cudaFuncAttributeMaxDynamicSharedMemorySize, SMEM_K64);

    // 1. fold weights
    fold_kernel<<<128, 128>>>(Wc_a, Wp_a, Wr_ma, bp_a, bc_a, br_ma);

    // 2. m2 = bf16(x_m @ W2^T + b2)
    mma_gemm_kernel<64, true><<<(NM + 127) / 128, 256, SMEM_K64>>>(
        x_merchant, NM, pW2h, pb2, pm2);

    // 3. acc = x_a @ W1^T + b1   (fp32 out)
    mma_gemm_kernel<128, false><<<(NA + 127) / 128, 256, SMEM_K128>>>(
        x_account, NA, pW1h, pb1, pacc);

    // 4. scatter edges — single pass, 32 edges per warp
    {
        int warps  = (E + 31) / 32;
        int blocks = (warps + 7) / 8;          // 8 warps per 256-thread block
        scatter_kernel<<<blocks, 256>>>(e_ma_src, e_ma_dst, e_ma_w, pm2, pacc, E);
    }

    // 5. head
    head_kernel<<<(NA + 7) / 8, 256>>>(pacc, Wo, bo, out, NA);
}

// round 5
// speedup vs baseline: 3.6259x; 1.1531x over previous
#include <cuda_runtime.h>
#include <cuda_bf16.h>
#include <cstdint>

#define Hh 128
#define DAa 128
#define DMm 64
#define NA_MAX 200000
#define NM_MAX 100000
#define E_MAX 1000000

// ---------------- device scratch (allocation-free: device globals) ----------------
__device__ float         g_b1[Hh];
__device__ float         g_b2[Hh];
__device__ __nv_bfloat16 g_W1h[Hh * DAa];        // 32 KB
__device__ __nv_bfloat16 g_W2h[Hh * DMm];        // 16 KB
__device__ __nv_bfloat16 g_m2[NM_MAX * Hh];      // 25.6 MB  m2 (bf16)
__device__ float         g_acc[NA_MAX * Hh];     // 102.4 MB proj+bias (read-only after GEMM3)
__device__ int           g_deg[NA_MAX];          // degree histogram
__device__ int           g_off[NA_MAX];          // CSR offsets (exclusive scan)
__device__ int           g_cnt[NA_MAX];          // placement cursors
__device__ int2          g_epk[E_MAX];           // dst-grouped (src, w_bits)
__device__ int           g_bsum[256];            // scan block sums
__device__ int           g_bofs[256];            // scanned block sums

__device__ __forceinline__ uint32_t smem_u32(const void* p) {
    uint32_t a;
    asm("{ .reg .u64 t; cvta.to.shared.u64 t, %1; cvt.u32.u64 %0, t; }" : "=r"(a) : "l"(p));
    return a;
}

#define LDMATRIX_X4(r0, r1, r2, r3, addr) \
    asm volatile("ldmatrix.sync.aligned.m8n8.x4.shared.b16 {%0,%1,%2,%3}, [%4];" \
                 : "=r"(r0), "=r"(r1), "=r"(r2), "=r"(r3) : "r"(addr))

#define MMA_BF16(c, a0, a1, a2, a3, b0, b1) \
    asm volatile("mma.sync.aligned.m16n8k16.row.col.f32.bf16.bf16.f32 " \
                 "{%0,%1,%2,%3}, {%4,%5,%6,%7}, {%8,%9}, {%0,%1,%2,%3};" \
                 : "+f"((c)[0]), "+f"((c)[1]), "+f"((c)[2]), "+f"((c)[3]) \
                 : "r"(a0), "r"(a1), "r"(a2), "r"(a3), "r"(b0), "r"(b1))

// ---------------- kernel 1: fold the linear chain ----------------
__global__ void fold_kernel(const float* __restrict__ Wc_a,
                            const float* __restrict__ Wp_a,
                            const float* __restrict__ Wr_ma,
                            const float* __restrict__ bp_a,
                            const float* __restrict__ bc_a,
                            const float* __restrict__ br_ma) {
    int h = blockIdx.x;        // 0..127
    int d = threadIdx.x;       // 0..127
    const float* wc1 = Wc_a + h * 256;
    const float* wc2 = wc1 + 128;

    float s = 0.f;
    #pragma unroll 8
    for (int k = 0; k < 128; ++k) s += wc1[k] * Wp_a[k * DAa + d];
    g_W1h[h * DAa + d] = __float2bfloat16(s);

    if (d < DMm) {
        float s2 = 0.f;
        #pragma unroll 8
        for (int k = 0; k < 128; ++k) s2 += wc2[k] * Wr_ma[k * DMm + d];
        g_W2h[h * DMm + d] = __float2bfloat16(s2);
    }
    if (d == 0) {
        float t1 = bc_a[h], t2 = 0.f;
        for (int k = 0; k < 128; ++k) {
            t1 += wc1[k] * bp_a[k];
            t2 += wc2[k] * br_ma[k];
        }
        g_b1[h] = t1;
        g_b2[h] = t2;
    }
}

// ---------------- kernels 2/3: warp-MMA GEMM  C[M,128] = bf16(A[M,K]) @ Wh^T + bias ----
template <int K, bool OUT_BF16>
__global__ void __launch_bounds__(256)
mma_gemm_kernel(const float* __restrict__ A, int M,
                const __nv_bfloat16* __restrict__ W,
                const float* __restrict__ bias,
                void* __restrict__ Cout) {
    constexpr int RS = K * 2 + 16;
    constexpr int TILE_B = 128 * RS;
    constexpr int WPR = K / 2;
    extern __shared__ char smem[];
    char*  smA   = smem;
    char*  smW   = smem + TILE_B;
    float* sbias = (float*)(smem + 2 * TILE_B);

    const int tid = threadIdx.x, wid = tid >> 5, lane = tid & 31;
    const int row0 = blockIdx.x * 128;

    for (int idx = tid; idx < 128 * WPR; idx += 256) {
        int r = idx / WPR, p = idx - r * WPR;
        *(uint32_t*)(smW + r * RS + p * 4) = ((const uint32_t*)W)[idx];
    }
    for (int idx = tid; idx < 128 * WPR; idx += 256) {
        int r = idx / WPR, p = idx - r * WPR;
        int gr = row0 + r;
        float2 av = (gr < M) ? ((const float2*)(A + (size_t)gr * K))[p]
                             : make_float2(0.f, 0.f);
        uint32_t pv;
        asm("cvt.rn.bf16x2.f32 %0, %1, %2;" : "=r"(pv) : "f"(av.y), "f"(av.x));
        *(uint32_t*)(smA + r * RS + p * 4) = pv;
    }
    if (tid < 128) sbias[tid] = bias[tid];
    __syncthreads();

    const uint32_t aBase = smem_u32(smA)
        + (uint32_t)(wid * 16 + (lane & 15)) * RS + (uint32_t)(lane >> 4) * 16;
    const uint32_t bBase = smem_u32(smW)
        + (uint32_t)((lane & 7) + ((lane >> 4) << 3)) * RS
        + (uint32_t)((lane >> 3) & 1) * 16;

    float acc[16][4];
    #pragma unroll
    for (int i = 0; i < 16; ++i)
        #pragma unroll
        for (int j = 0; j < 4; ++j) acc[i][j] = 0.f;

    #pragma unroll
    for (int ks = 0; ks < K / 16; ++ks) {
        uint32_t a0, a1, a2, a3;
        LDMATRIX_X4(a0, a1, a2, a3, aBase + (uint32_t)ks * 32);
        #pragma unroll
        for (int jp = 0; jp < 8; ++jp) {
            uint32_t b0, b1, b2, b3;
            LDMATRIX_X4(b0, b1, b2, b3, bBase + (uint32_t)(jp * 16) * RS + (uint32_t)ks * 32);
            MMA_BF16(acc[2 * jp],     a0, a1, a2, a3, b0, b1);
            MMA_BF16(acc[2 * jp + 1], a0, a1, a2, a3, b2, b3);
        }
    }

    const int g = lane >> 2, t = lane & 3;
    const int r_lo = row0 + wid * 16 + g;
    const int r_hi = r_lo + 8;
    const bool lo_ok = r_lo < M, hi_ok = r_hi < M;

    #pragma unroll
    for (int nt = 0; nt < 16; ++nt) {
        int col = nt * 8 + 2 * t;
        float bx = sbias[col], by = sbias[col + 1];
        float c0 = acc[nt][0] + bx, c1 = acc[nt][1] + by;
        float c2 = acc[nt][2] + bx, c3 = acc[nt][3] + by;
        if (OUT_BF16) {
            __nv_bfloat16* C = (__nv_bfloat16*)Cout;
            uint32_t plo, phi;
            asm("cvt.rn.bf16x2.f32 %0, %1, %2;" : "=r"(plo) : "f"(c1), "f"(c0));
            asm("cvt.rn.bf16x2.f32 %0, %1, %2;" : "=r"(phi) : "f"(c3), "f"(c2));
            if (lo_ok) *(uint32_t*)(C + (size_t)r_lo * 128 + col) = plo;
            if (hi_ok) *(uint32_t*)(C + (size_t)r_hi * 128 + col) = phi;
        } else {
            float* C = (float*)Cout;
            if (lo_ok) *(float2*)(C + (size_t)r_lo * 128 + col) = make_float2(c0, c1);
            if (hi_ok) *(float2*)(C + (size_t)r_hi * 128 + col) = make_float2(c2, c3);
        }
    }
}

// ---------------- CSR build ----------------
__global__ void zero2_kernel(int* a, int* b, int n) {
    int i = blockIdx.x * blockDim.x + threadIdx.x;
    if (i < n) { a[i] = 0; b[i] = 0; }
}

__global__ void hist_kernel(const int* __restrict__ dst, int E, int* __restrict__ deg) {
    int i = blockIdx.x * blockDim.x + threadIdx.x;
    if (i < E) atomicAdd(&deg[dst[i]], 1);
}

// exclusive scan, 1024 elements per 1024-thread block; writes block total
__global__ void scan1_kernel(const int* __restrict__ in, int n,
                             int* __restrict__ out, int* __restrict__ bsum) {
    __shared__ int sh[1024];
    int i = blockIdx.x * 1024 + threadIdx.x;
    int v = (i < n) ? in[i] : 0;
    sh[threadIdx.x] = v;
    __syncthreads();
    #pragma unroll
    for (int off = 1; off < 1024; off <<= 1) {
        int t = (threadIdx.x >= off) ? sh[threadIdx.x - off] : 0;
        __syncthreads();
        sh[threadIdx.x] += t;
        __syncthreads();
    }
    if (i < n) out[i] = sh[threadIdx.x] - v;     // exclusive
    if (bsum && threadIdx.x == 1023) bsum[blockIdx.x] = sh[1023];
}

__global__ void scan3_kernel(int* __restrict__ out, int n, const int* __restrict__ bofs) {
    int i = blockIdx.x * blockDim.x + threadIdx.x;
    if (i < n) out[i] += bofs[i >> 10];
}

__global__ void place_kernel(const int* __restrict__ src, const int* __restrict__ dst,
                             const float* __restrict__ w, int E,
                             const int* __restrict__ off, int* __restrict__ cnt,
                             int2* __restrict__ epk) {
    int i = blockIdx.x * blockDim.x + threadIdx.x;
    if (i >= E) return;
    int d = dst[i];
    int p = off[d] + atomicAdd(&cnt[d], 1);
    epk[p] = make_int2(src[i], __float_as_int(w[i]));
}

// ---------------- fused gather-reduce + head, one warp per account ----------------
// z = acc[i] + sum_e w_e * m2[src_e];  out[i] = sigmoid(Wo . relu(z) + bo)
__global__ void __launch_bounds__(256)
gather_head_kernel(const float* __restrict__ acc,
                   const int* __restrict__ off,
                   const int2* __restrict__ epk,
                   const __nv_bfloat16* __restrict__ m2,
                   const float* __restrict__ Wo,
                   const float* __restrict__ bo,
                   float* __restrict__ out, int NA, int E) {
    const int warp = (blockIdx.x * blockDim.x + threadIdx.x) >> 5;
    const int lane = threadIdx.x & 31;
    if (warp >= NA) return;

    const int a = off[warp];
    const int b = (warp + 1 < NA) ? off[warp + 1] : E;

    float4 z = ((const float4*)(acc + (size_t)warp * 128))[lane];

    int e = a;
    int2 pk = (e < b) ? __ldg(&epk[e]) : make_int2(0, 0);
    while (e < b) {
        int2 cur = pk;
        ++e;
        if (e < b) pk = __ldg(&epk[e]);
        float wf = __int_as_float(cur.y);
        uint2 q = *(const uint2*)((const char*)m2 + (size_t)cur.x * 256 + lane * 8);
        __nv_bfloat162 b0 = *reinterpret_cast<__nv_bfloat162*>(&q.x);
        __nv_bfloat162 b1 = *reinterpret_cast<__nv_bfloat162*>(&q.y);
        float2 f0 = __bfloat1622float2(b0);
        float2 f1 = __bfloat1622float2(b1);
        z.x = fmaf(f0.x, wf, z.x);
        z.y = fmaf(f0.y, wf, z.y);
        z.z = fmaf(f1.x, wf, z.z);
        z.w = fmaf(f1.y, wf, z.w);
    }

    float4 wv = ((const float4*)Wo)[lane];
    float p = fmaxf(z.x, 0.f) * wv.x + fmaxf(z.y, 0.f) * wv.y +
              fmaxf(z.z, 0.f) * wv.z + fmaxf(z.w, 0.f) * wv.w;
    #pragma unroll
    for (int o = 16; o > 0; o >>= 1)
        p += __shfl_xor_sync(0xFFFFFFFFu, p, o);
    if (lane == 0) {
        float zz = p + bo[0];
        out[warp] = 1.f / (1.f + expf(-zz));
    }
}

// ---------------- launch ----------------
extern "C" void kernel_launch(void* const* d_in, const int* in_sizes, int n_in,
                              void* d_out, int out_size) {
    const float* x_account  = (const float*)d_in[0];
    const float* x_merchant = (const float*)d_in[1];
    const int*   e_ma_src = (const int*)d_in[5];
    const int*   e_ma_dst = (const int*)d_in[6];
    const float* e_ma_w   = (const float*)d_in[7];
    const float* Wp_a  = (const float*)d_in[8];
    const float* bp_a  = (const float*)d_in[9];
    const float* Wr_ma = (const float*)d_in[14];
    const float* br_ma = (const float*)d_in[15];
    const float* Wc_a  = (const float*)d_in[16];
    const float* bc_a  = (const float*)d_in[17];
    const float* Wo = (const float*)d_in[20];
    const float* bo = (const float*)d_in[21];
    float* out = (float*)d_out;

    const int NA = in_sizes[0] / DAa;   // 200000
    const int NM = in_sizes[1] / DMm;   // 100000
    const int E  = in_sizes[5];         // 1000000

    float *pb1, *pb2, *pacc;
    __nv_bfloat16 *pW1h, *pW2h, *pm2;
    int *pdeg, *poff, *pcnt, *pbsum, *pbofs;
    int2 *pepk;
    cudaGetSymbolAddress((void**)&pb1, g_b1);
    cudaGetSymbolAddress((void**)&pb2, g_b2);
    cudaGetSymbolAddress((void**)&pW1h, g_W1h);
    cudaGetSymbolAddress((void**)&pW2h, g_W2h);
    cudaGetSymbolAddress((void**)&pm2, g_m2);
    cudaGetSymbolAddress((void**)&pacc, g_acc);
    cudaGetSymbolAddress((void**)&pdeg, g_deg);
    cudaGetSymbolAddress((void**)&poff, g_off);
    cudaGetSymbolAddress((void**)&pcnt, g_cnt);
    cudaGetSymbolAddress((void**)&pbsum, g_bsum);
    cudaGetSymbolAddress((void**)&pbofs, g_bofs);
    cudaGetSymbolAddress((void**)&pepk, g_epk);

    constexpr int SMEM_K128 = 2 * 128 * (128 * 2 + 16) + 512;   // 70144 B
    constexpr int SMEM_K64  = 2 * 128 * (64 * 2 + 16) + 512;    // 37376 B
    cudaFuncSetAttribute(mma_gemm_kernel<128, false>,
                         cudaFuncAttributeMaxDynamicSharedMemorySize, SMEM_K128);
    cudaFuncSetAttribute(mma_gemm_kernel<64, true>,
                         cudaFuncAttributeMaxDynamicSharedMemorySize, SMEM_K64);

    // --- CSR build (independent of GEMMs; issue first for overlap potential) ---
    zero2_kernel<<<(NA + 255) / 256, 256>>>(pdeg, pcnt, NA);
    hist_kernel<<<(E + 255) / 256, 256>>>(e_ma_dst, E, pdeg);
    {
        int nblk = (NA + 1023) / 1024;           // 196
        scan1_kernel<<<nblk, 1024>>>(pdeg, NA, poff, pbsum);
        scan1_kernel<<<1, 1024>>>(pbsum, nblk, pbofs, nullptr);
        scan3_kernel<<<(NA + 255) / 256, 256>>>(poff, NA, pbofs);
    }
    place_kernel<<<(E + 255) / 256, 256>>>(e_ma_src, e_ma_dst, e_ma_w, E, poff, pcnt, pepk);

    // --- weights + GEMMs ---
    fold_kernel<<<128, 128>>>(Wc_a, Wp_a, Wr_ma, bp_a, bc_a, br_ma);
    mma_gemm_kernel<64, true><<<(NM + 127) / 128, 256, SMEM_K64>>>(
        x_merchant, NM, pW2h, pb2, pm2);
    mma_gemm_kernel<128, false><<<(NA + 127) / 128, 256, SMEM_K128>>>(
        x_account, NA, pW1h, pb1, pacc);

    // --- fused gather-reduce + head ---
    gather_head_kernel<<<(NA + 7) / 8, 256>>>(pacc, poff, pepk, pm2, Wo, bo, out, NA, E);
}